// round 13
// baseline (speedup 1.0000x reference)
#include <cuda_runtime.h>

#define RAD 3
#define WIN 49            // (2*RAD+1)^2
#define NN  128
#define KCH 131
#define CCH 21
#define BB  2
#define NS  7             // k-slices

// ---------------- scratch ----------------
__device__ float g_Apart[NS * BB * WIN * NN * NN];  // 44.8 MB partials
__device__ float g_A    [BB * WIN * NN * NN];       // 6.4 MB reduced

// ================= kernel 1: per-pixel window weights =================
// Window split across half-warps: lanes 0-15 handle w in [0,25),
// lanes 16-31 handle w in [25,49) for the SAME 16 pixels.
// e = exp(|v_c - v_n|) = max(E_n*R_c, R_n*E_c),  E=exp(v), R=exp(-v),
// halo-out-of-grid cells carry (E,R)=(0,0)  (== reference `valid` mask).

#define T1H 8
#define T1W 16
#define NT1 256                   // 2 threads per pixel
#define H1H (T1H + 2 * RAD)       // 14
#define H1W (T1W + 2 * RAD)       // 22
#define HSZ (H1H * H1W)           // 308
#define NFILL ((HSZ + NT1 - 1) / NT1)   // 2
#define NWMAX 25

template<int W0, int NW>
__device__ __forceinline__ void win_body(const unsigned long long* __restrict__ sb,
                                         int base, unsigned long long cs,
                                         float* __restrict__ ew, float* __restrict__ ss)
{
    #pragma unroll
    for (int i = 0; i < NW; i++) {
        const int w  = W0 + i;
        const int oi = w / 7, oj = w % 7;
        unsigned long long nb = sb[base + oi * H1W + oj];
        unsigned long long p;
        asm("mul.rn.f32x2 %0, %1, %2;" : "=l"(p) : "l"(nb), "l"(cs));
        float e = fmaxf(__uint_as_float((unsigned)p),
                        __uint_as_float((unsigned)(p >> 32)));
        ew[i] = e;
        ss[i & 3] += e;
    }
}

__global__ __launch_bounds__(NT1)
void rwn_weights_kernel(const float* __restrict__ feats,   // [B,K,N,N]
                        const int*   __restrict__ mask,    // [B,N,N]
                        const float* __restrict__ cp)      // [K]
{
    __shared__ float2 sER[2][HSZ];

    const int z  = blockIdx.z;
    const int b  = z % BB;
    const int sl = z / BB;
    const int bi = blockIdx.y * T1H;
    const int bj = blockIdx.x * T1W;
    const int t    = threadIdx.x;
    const int lane = t & 31;
    const int half = lane >> 4;            // 0: w 0..24, 1: w 25..48
    const int ti   = t >> 5;               // warp id == tile row (8 warps)
    const int tj   = lane & 15;            // pixel column within tile
    const int gi = bi + ti, gj = bj + tj;

    const int kbeg = (sl * KCH) / NS;
    const int kend = ((sl + 1) * KCH) / NS;

    const int*   mb = mask  + b * NN * NN;
    const float* fb = feats + (size_t)b * KCH * NN * NN;

    // smem-fill slots
    int   foff[NFILL];
    float fmsk[NFILL];
    bool  fok [NFILL];
    #pragma unroll
    for (int s = 0; s < NFILL; s++) {
        int idx = t + s * NT1;
        foff[s] = 0; fmsk[s] = 0.f; fok[s] = false;
        if (idx < HSZ) {
            int hi = idx / H1W, hj = idx % H1W;
            int ggi = bi + hi - RAD, ggj = bj + hj - RAD;
            if (ggi >= 0 && ggi < NN && ggj >= 0 && ggj < NN) {
                fok[s]  = true;
                foff[s] = ggi * NN + ggj;
                fmsk[s] = (float)mb[foff[s]];
            }
        }
    }
    const float myM = (float)mb[gi * NN + gj];
    const int   wbase = ti * H1W + tj;      // window origin in halo tile

    float Aw[NWMAX];
    #pragma unroll
    for (int w = 0; w < NWMAX; w++) Aw[w] = 0.f;

    // prologue fill: buffer 0 <- k = kbeg
    {
        const float* fk = fb + (size_t)kbeg * NN * NN;
        #pragma unroll
        for (int s = 0; s < NFILL; s++) {
            int idx = t + s * NT1;
            if (idx < HSZ) {
                float ex = 0.f, rx = 0.f;
                if (fok[s]) {
                    float v = __ldg(fk + foff[s]) * fmsk[s];
                    ex = __expf(v);
                    rx = __expf(-v);
                }
                sER[0][idx] = make_float2(ex, rx);
            }
        }
    }
    __syncthreads();

    #pragma unroll 1
    for (int k = kbeg; k < kend; k++) {
        const int cur = (k - kbeg) & 1;

        // prefetch next k into other buffer
        if (k + 1 < kend) {
            const float* fk = fb + (size_t)(k + 1) * NN * NN;
            #pragma unroll
            for (int s = 0; s < NFILL; s++) {
                int idx = t + s * NT1;
                if (idx < HSZ) {
                    float ex = 0.f, rx = 0.f;
                    if (fok[s]) {
                        float v = __ldg(fk + foff[s]) * fmsk[s];
                        ex = __expf(v);
                        rx = __expf(-v);
                    }
                    sER[cur ^ 1][idx] = make_float2(ex, rx);
                }
            }
        }

        {
            const float2 c = sER[cur][(ti + RAD) * H1W + (tj + RAD)];
            // packed (lo=R_c, hi=E_c): lo multiplies E_n, hi multiplies R_n
            const unsigned long long cs =
                (unsigned long long)__float_as_uint(c.y) |
                ((unsigned long long)__float_as_uint(c.x) << 32);
            const unsigned long long* sb =
                (const unsigned long long*)&sER[cur][0];

            float ew[NWMAX];
            ew[NWMAX - 1] = 0.f;            // half 1 leaves slot 24 unused
            float ss[4] = {0.f, 0.f, 0.f, 0.f};
            if (half == 0) win_body< 0, 25>(sb, wbase, cs, ew, ss);
            else           win_body<25, 24>(sb, wbase, cs, ew, ss);

            float ssl  = (ss[0] + ss[1]) + (ss[2] + ss[3]);
            float ssum = ssl + __shfl_xor_sync(0xFFFFFFFFu, ssl, 16);

            float scale = __fdividef(__ldg(cp + k), ssum);
            if (myM == 0.f) scale = 0.f;
            #pragma unroll
            for (int i = 0; i < NWMAX; i++) Aw[i] += scale * ew[i];
        }
        __syncthreads();
    }

    float* Ab = g_Apart + ((size_t)sl * BB + b) * WIN * NN * NN
              + gi * NN + gj;
    if (half == 0) {
        #pragma unroll
        for (int i = 0; i < 25; i++)
            Ab[(size_t)i * NN * NN] = Aw[i];
    } else {
        #pragma unroll
        for (int i = 0; i < 24; i++)
            Ab[(size_t)(25 + i) * NN * NN] = Aw[i];
    }
}

// ================= reduce: g_A = sum over NS partials =================

#define RED_TOT4 (BB * WIN * NN * NN / 4)   // 401408 float4
#define RED_THR  256

__global__ __launch_bounds__(RED_THR)
void rwn_reduce_kernel()
{
    const int i = blockIdx.x * RED_THR + threadIdx.x;
    const float4* p = (const float4*)g_Apart;
    float4 r = p[i];
    #pragma unroll
    for (int s = 1; s < NS; s++) {
        float4 a = p[i + (size_t)s * RED_TOT4];
        r.x += a.x; r.y += a.y; r.z += a.z; r.w += a.w;
    }
    ((float4*)g_A)[i] = r;
}

// ================= kernel 2: gather (channel-grouped) =================

#define T2H 16
#define T2W 16
#define NT2 (T2H * T2W)
#define H2  (T2H + 2 * RAD)       // 22
#define CG  7                     // channels per block
#define NG  (CCH / CG)            // 3 groups

__global__ __launch_bounds__(NT2)
void rwn_gather_kernel(const float* __restrict__ x2,   // [B,C,N*N]
                       float* __restrict__ out)        // [B,N*N,C]
{
    __shared__ float sX[CG][H2 * H2];   // 13552 B

    const int z  = blockIdx.z;
    const int b  = z % BB;
    const int cg = z / BB;
    const int bi = blockIdx.y * T2H;
    const int bj = blockIdx.x * T2W;
    const int t  = threadIdx.x;
    const int ti = t / T2W, tj = t % T2W;
    const int qi = bi + ti, qj = bj + tj;

    const float* xb = x2 + ((size_t)b * CCH + cg * CG) * NN * NN;
    for (int idx = t; idx < CG * H2 * H2; idx += NT2) {
        int c  = idx / (H2 * H2);
        int r  = idx % (H2 * H2);
        int hi = r / H2, hj = r % H2;
        int gi = bi + hi - RAD, gj = bj + hj - RAD;
        float v = 0.f;
        if (gi >= 0 && gi < NN && gj >= 0 && gj < NN)
            v = __ldg(xb + c * NN * NN + gi * NN + gj);
        sX[c][r] = v;
    }
    __syncthreads();

    float acc[CG];
    #pragma unroll
    for (int c = 0; c < CG; c++) acc[c] = 0.f;

    const float* Ab = g_A + (size_t)b * WIN * NN * NN;

    #pragma unroll
    for (int oi = -RAD; oi <= RAD; oi++) {
        #pragma unroll
        for (int oj = -RAD; oj <= RAD; oj++) {
            const int w  = (oi + RAD) * (2 * RAD + 1) + (oj + RAD);
            const int pi = qi - oi, pj = qj - oj;
            if (pi < 0 || pi >= NN || pj < 0 || pj >= NN) continue;
            const float a = __ldg(Ab + (size_t)w * NN * NN + pi * NN + pj);
            const int sidx = (ti + RAD - oi) * H2 + (tj + RAD - oj);
            #pragma unroll
            for (int c = 0; c < CG; c++)
                acc[c] += a * sX[c][sidx];
        }
    }

    float* ob = out + ((size_t)b * NN * NN + qi * NN + qj) * CCH + cg * CG;
    #pragma unroll
    for (int c = 0; c < CG; c++) ob[c] = acc[c];
}

// ================= launch =================
extern "C" void kernel_launch(void* const* d_in, const int* in_sizes, int n_in,
                              void* d_out, int out_size)
{
    const float* feats = (const float*)d_in[0];   // intergrated [B,K,N,N]
    const float* x2    = (const float*)d_in[1];   // [B,C,N*N]
    const int*   mask  = (const int*)  d_in[2];   // [B,N,N]
    const float* cp    = (const float*)d_in[3];   // [K]
    float*       out   = (float*)d_out;           // [B,N*N,C]

    dim3 g1(NN / T1W, NN / T1H, BB * NS);     // (8,16,14) = 1792 blocks
    rwn_weights_kernel<<<g1, NT1>>>(feats, mask, cp);

    rwn_reduce_kernel<<<RED_TOT4 / RED_THR, RED_THR>>>();   // 1568 blocks

    dim3 g2(NN / T2W, NN / T2H, BB * NG);     // (8,8,6) = 384 blocks
    rwn_gather_kernel<<<g2, NT2>>>(x2, out);
}

// round 14
// speedup vs baseline: 1.0009x; 1.0009x over previous
#include <cuda_runtime.h>

#define RAD 3
#define WIN 49            // (2*RAD+1)^2
#define NN  128
#define KCH 131
#define CCH 21
#define BB  2
#define NS  7             // k-slices

// ---------------- scratch ----------------
__device__ float g_Apart[NS * BB * WIN * NN * NN];  // 44.8 MB partials
__device__ float g_A    [BB * WIN * NN * NN];       // 6.4 MB reduced

// ================= kernel 1: per-pixel window weights =================
// Window split across half-warps: lanes 0-15 handle w in [0,25),
// lanes 16-31 handle w in [25,49) for the SAME 16 pixels.
// e = exp(|v_c - v_n|) = max(E_n*R_c, R_n*E_c),  E=exp(v), R=exp(-v),
// halo-out-of-grid cells carry (E,R)=(0,0)  (== reference `valid` mask).

#define T1H 8
#define T1W 16
#define NT1 256                   // 2 threads per pixel
#define H1H (T1H + 2 * RAD)       // 14
#define H1W (T1W + 2 * RAD)       // 22
#define HSZ (H1H * H1W)           // 308
#define NFILL ((HSZ + NT1 - 1) / NT1)   // 2
#define NWMAX 25

template<int W0, int NW>
__device__ __forceinline__ void win_body(const unsigned long long* __restrict__ sb,
                                         int base, unsigned long long cs,
                                         float* __restrict__ ew, float* __restrict__ ss)
{
    #pragma unroll
    for (int i = 0; i < NW; i++) {
        const int w  = W0 + i;
        const int oi = w / 7, oj = w % 7;
        unsigned long long nb = sb[base + oi * H1W + oj];
        unsigned long long p;
        asm("mul.rn.f32x2 %0, %1, %2;" : "=l"(p) : "l"(nb), "l"(cs));
        float e = fmaxf(__uint_as_float((unsigned)p),
                        __uint_as_float((unsigned)(p >> 32)));
        ew[i] = e;
        ss[i & 3] += e;
    }
}

__global__ __launch_bounds__(NT1)
void rwn_weights_kernel(const float* __restrict__ feats,   // [B,K,N,N]
                        const int*   __restrict__ mask,    // [B,N,N]
                        const float* __restrict__ cp)      // [K]
{
    __shared__ float2 sER[2][HSZ];

    const int z  = blockIdx.z;
    const int b  = z % BB;
    const int sl = z / BB;
    const int bi = blockIdx.y * T1H;
    const int bj = blockIdx.x * T1W;
    const int t    = threadIdx.x;
    const int lane = t & 31;
    const int half = lane >> 4;            // 0: w 0..24, 1: w 25..48
    const int ti   = t >> 5;               // warp id == tile row (8 warps)
    const int tj   = lane & 15;            // pixel column within tile
    const int gi = bi + ti, gj = bj + tj;

    const int kbeg = (sl * KCH) / NS;
    const int kend = ((sl + 1) * KCH) / NS;

    const int*   mb = mask  + b * NN * NN;
    const float* fb = feats + (size_t)b * KCH * NN * NN;

    // smem-fill slots
    int   foff[NFILL];
    float fmsk[NFILL];
    bool  fok [NFILL];
    #pragma unroll
    for (int s = 0; s < NFILL; s++) {
        int idx = t + s * NT1;
        foff[s] = 0; fmsk[s] = 0.f; fok[s] = false;
        if (idx < HSZ) {
            int hi = idx / H1W, hj = idx % H1W;
            int ggi = bi + hi - RAD, ggj = bj + hj - RAD;
            if (ggi >= 0 && ggi < NN && ggj >= 0 && ggj < NN) {
                fok[s]  = true;
                foff[s] = ggi * NN + ggj;
                fmsk[s] = (float)mb[foff[s]];
            }
        }
    }
    const float myM = (float)mb[gi * NN + gj];
    const int   wbase = ti * H1W + tj;      // window origin in halo tile

    float Aw[NWMAX];
    #pragma unroll
    for (int w = 0; w < NWMAX; w++) Aw[w] = 0.f;

    // prologue fill: buffer 0 <- k = kbeg
    {
        const float* fk = fb + (size_t)kbeg * NN * NN;
        #pragma unroll
        for (int s = 0; s < NFILL; s++) {
            int idx = t + s * NT1;
            if (idx < HSZ) {
                float ex = 0.f, rx = 0.f;
                if (fok[s]) {
                    float v = __ldg(fk + foff[s]) * fmsk[s];
                    ex = __expf(v);
                    rx = __expf(-v);
                }
                sER[0][idx] = make_float2(ex, rx);
            }
        }
    }
    __syncthreads();

    #pragma unroll 1
    for (int k = kbeg; k < kend; k++) {
        const int cur = (k - kbeg) & 1;

        // prefetch next k into other buffer
        if (k + 1 < kend) {
            const float* fk = fb + (size_t)(k + 1) * NN * NN;
            #pragma unroll
            for (int s = 0; s < NFILL; s++) {
                int idx = t + s * NT1;
                if (idx < HSZ) {
                    float ex = 0.f, rx = 0.f;
                    if (fok[s]) {
                        float v = __ldg(fk + foff[s]) * fmsk[s];
                        ex = __expf(v);
                        rx = __expf(-v);
                    }
                    sER[cur ^ 1][idx] = make_float2(ex, rx);
                }
            }
        }

        {
            const float2 c = sER[cur][(ti + RAD) * H1W + (tj + RAD)];
            // packed (lo=R_c, hi=E_c): lo multiplies E_n, hi multiplies R_n
            const unsigned long long cs =
                (unsigned long long)__float_as_uint(c.y) |
                ((unsigned long long)__float_as_uint(c.x) << 32);
            const unsigned long long* sb =
                (const unsigned long long*)&sER[cur][0];

            float ew[NWMAX];
            ew[NWMAX - 1] = 0.f;            // half 1 leaves slot 24 unused
            float ss[4] = {0.f, 0.f, 0.f, 0.f};
            if (half == 0) win_body< 0, 25>(sb, wbase, cs, ew, ss);
            else           win_body<25, 24>(sb, wbase, cs, ew, ss);

            float ssl  = (ss[0] + ss[1]) + (ss[2] + ss[3]);
            float ssum = ssl + __shfl_xor_sync(0xFFFFFFFFu, ssl, 16);

            float scale = __fdividef(__ldg(cp + k), ssum);
            if (myM == 0.f) scale = 0.f;
            #pragma unroll
            for (int i = 0; i < NWMAX; i++) Aw[i] += scale * ew[i];
        }
        __syncthreads();
    }

    float* Ab = g_Apart + ((size_t)sl * BB + b) * WIN * NN * NN
              + gi * NN + gj;
    if (half == 0) {
        #pragma unroll
        for (int i = 0; i < 25; i++)
            Ab[(size_t)i * NN * NN] = Aw[i];
    } else {
        #pragma unroll
        for (int i = 0; i < 24; i++)
            Ab[(size_t)(25 + i) * NN * NN] = Aw[i];
    }
}

// ================= reduce: g_A = sum over NS partials =================

#define RED_TOT4 (BB * WIN * NN * NN / 4)   // 401408 float4
#define RED_THR  256

__global__ __launch_bounds__(RED_THR)
void rwn_reduce_kernel()
{
    const int i = blockIdx.x * RED_THR + threadIdx.x;
    const float4* p = (const float4*)g_Apart;
    float4 r = p[i];
    #pragma unroll
    for (int s = 1; s < NS; s++) {
        float4 a = p[i + (size_t)s * RED_TOT4];
        r.x += a.x; r.y += a.y; r.z += a.z; r.w += a.w;
    }
    ((float4*)g_A)[i] = r;
}

// ================= kernel 2: gather (channel-grouped) =================

#define T2H 16
#define T2W 16
#define NT2 (T2H * T2W)
#define H2  (T2H + 2 * RAD)       // 22
#define CG  7                     // channels per block
#define NG  (CCH / CG)            // 3 groups

__global__ __launch_bounds__(NT2)
void rwn_gather_kernel(const float* __restrict__ x2,   // [B,C,N*N]
                       float* __restrict__ out)        // [B,N*N,C]
{
    __shared__ float sX[CG][H2 * H2];   // 13552 B

    const int z  = blockIdx.z;
    const int b  = z % BB;
    const int cg = z / BB;
    const int bi = blockIdx.y * T2H;
    const int bj = blockIdx.x * T2W;
    const int t  = threadIdx.x;
    const int ti = t / T2W, tj = t % T2W;
    const int qi = bi + ti, qj = bj + tj;

    const float* xb = x2 + ((size_t)b * CCH + cg * CG) * NN * NN;
    for (int idx = t; idx < CG * H2 * H2; idx += NT2) {
        int c  = idx / (H2 * H2);
        int r  = idx % (H2 * H2);
        int hi = r / H2, hj = r % H2;
        int gi = bi + hi - RAD, gj = bj + hj - RAD;
        float v = 0.f;
        if (gi >= 0 && gi < NN && gj >= 0 && gj < NN)
            v = __ldg(xb + c * NN * NN + gi * NN + gj);
        sX[c][r] = v;
    }
    __syncthreads();

    float acc[CG];
    #pragma unroll
    for (int c = 0; c < CG; c++) acc[c] = 0.f;

    const float* Ab = g_A + (size_t)b * WIN * NN * NN;

    #pragma unroll
    for (int oi = -RAD; oi <= RAD; oi++) {
        #pragma unroll
        for (int oj = -RAD; oj <= RAD; oj++) {
            const int w  = (oi + RAD) * (2 * RAD + 1) + (oj + RAD);
            const int pi = qi - oi, pj = qj - oj;
            if (pi < 0 || pi >= NN || pj < 0 || pj >= NN) continue;
            const float a = __ldg(Ab + (size_t)w * NN * NN + pi * NN + pj);
            const int sidx = (ti + RAD - oi) * H2 + (tj + RAD - oj);
            #pragma unroll
            for (int c = 0; c < CG; c++)
                acc[c] += a * sX[c][sidx];
        }
    }

    float* ob = out + ((size_t)b * NN * NN + qi * NN + qj) * CCH + cg * CG;
    #pragma unroll
    for (int c = 0; c < CG; c++) ob[c] = acc[c];
}

// ================= launch =================
extern "C" void kernel_launch(void* const* d_in, const int* in_sizes, int n_in,
                              void* d_out, int out_size)
{
    const float* feats = (const float*)d_in[0];   // intergrated [B,K,N,N]
    const float* x2    = (const float*)d_in[1];   // [B,C,N*N]
    const int*   mask  = (const int*)  d_in[2];   // [B,N,N]
    const float* cp    = (const float*)d_in[3];   // [K]
    float*       out   = (float*)d_out;           // [B,N*N,C]

    dim3 g1(NN / T1W, NN / T1H, BB * NS);     // (8,16,14) = 1792 blocks
    rwn_weights_kernel<<<g1, NT1>>>(feats, mask, cp);

    rwn_reduce_kernel<<<RED_TOT4 / RED_THR, RED_THR>>>();   // 1568 blocks

    dim3 g2(NN / T2W, NN / T2H, BB * NG);     // (8,8,6) = 384 blocks
    rwn_gather_kernel<<<g2, NT2>>>(x2, out);
}

// round 15
// speedup vs baseline: 1.2556x; 1.2545x over previous
#include <cuda_runtime.h>

#define RAD 3
#define WIN 49            // (2*RAD+1)^2
#define NN  128
#define KCH 131
#define CCH 21
#define BB  2
#define NS  7             // k-slices

// ---------------- scratch ----------------
__device__ float g_Apart[NS * BB * WIN * NN * NN];  // 44.8 MB partials
__device__ float g_A    [BB * WIN * NN * NN];       // 6.4 MB reduced

// ================= kernel 1: per-pixel window weights =================
// Lane-UNIFORM half-warp window split: lane half h handles w = 2*i + h,
// i in [0,25). No divergent branches — per-lane smem offset is a SEL
// between two compile-time constants.
// e = exp(|v_c - v_n|) = max(E_n*R_c, R_n*E_c),  E=exp(v), R=exp(-v),
// halo-out-of-grid cells carry (E,R)=(0,0)  (== reference `valid` mask).

#define T1H 8
#define T1W 16
#define NT1 256                   // 2 threads per pixel
#define H1H (T1H + 2 * RAD)       // 14
#define H1W (T1W + 2 * RAD)       // 22
#define HSZ (H1H * H1W)           // 308
#define NFILL ((HSZ + NT1 - 1) / NT1)   // 2
#define NWT 25                    // windows per thread (half 1 uses 24)

__global__ __launch_bounds__(NT1)
void rwn_weights_kernel(const float* __restrict__ feats,   // [B,K,N,N]
                        const int*   __restrict__ mask,    // [B,N,N]
                        const float* __restrict__ cp)      // [K]
{
    __shared__ float2 sER[2][HSZ];

    const int z  = blockIdx.z;
    const int b  = z % BB;
    const int sl = z / BB;
    const int bi = blockIdx.y * T1H;
    const int bj = blockIdx.x * T1W;
    const int t    = threadIdx.x;
    const int lane = t & 31;
    const bool odd = (lane & 16) != 0;     // half: even vs odd windows
    const int ti   = t >> 5;               // warp id == tile row (8 warps)
    const int tj   = lane & 15;            // pixel column within tile
    const int gi = bi + ti, gj = bj + tj;

    const int kbeg = (sl * KCH) / NS;
    const int kend = ((sl + 1) * KCH) / NS;

    const int*   mb = mask  + b * NN * NN;
    const float* fb = feats + (size_t)b * KCH * NN * NN;

    // smem-fill slots
    int   foff[NFILL];
    float fmsk[NFILL];
    bool  fok [NFILL];
    #pragma unroll
    for (int s = 0; s < NFILL; s++) {
        int idx = t + s * NT1;
        foff[s] = 0; fmsk[s] = 0.f; fok[s] = false;
        if (idx < HSZ) {
            int hi = idx / H1W, hj = idx % H1W;
            int ggi = bi + hi - RAD, ggj = bj + hj - RAD;
            if (ggi >= 0 && ggi < NN && ggj >= 0 && ggj < NN) {
                fok[s]  = true;
                foff[s] = ggi * NN + ggj;
                fmsk[s] = (float)mb[foff[s]];
            }
        }
    }
    const float myM = (float)mb[gi * NN + gj];
    const int   wbase = ti * H1W + tj;      // window origin in halo tile

    float Aw[NWT];
    #pragma unroll
    for (int w = 0; w < NWT; w++) Aw[w] = 0.f;

    // prologue fill: buffer 0 <- k = kbeg
    {
        const float* fk = fb + (size_t)kbeg * NN * NN;
        #pragma unroll
        for (int s = 0; s < NFILL; s++) {
            int idx = t + s * NT1;
            if (idx < HSZ) {
                float ex = 0.f, rx = 0.f;
                if (fok[s]) {
                    float v = __ldg(fk + foff[s]) * fmsk[s];
                    ex = __expf(v);
                    rx = __expf(-v);
                }
                sER[0][idx] = make_float2(ex, rx);
            }
        }
    }
    __syncthreads();

    #pragma unroll 1
    for (int k = kbeg; k < kend; k++) {
        const int cur = (k - kbeg) & 1;

        // prefetch next k into other buffer (LDGs issued before window compute)
        if (k + 1 < kend) {
            const float* fk = fb + (size_t)(k + 1) * NN * NN;
            #pragma unroll
            for (int s = 0; s < NFILL; s++) {
                int idx = t + s * NT1;
                if (idx < HSZ) {
                    float ex = 0.f, rx = 0.f;
                    if (fok[s]) {
                        float v = __ldg(fk + foff[s]) * fmsk[s];
                        ex = __expf(v);
                        rx = __expf(-v);
                    }
                    sER[cur ^ 1][idx] = make_float2(ex, rx);
                }
            }
        }

        {
            const float2 c = sER[cur][(ti + RAD) * H1W + (tj + RAD)];
            // packed (lo=R_c, hi=E_c): lo multiplies E_n, hi multiplies R_n
            const unsigned long long cs =
                (unsigned long long)__float_as_uint(c.y) |
                ((unsigned long long)__float_as_uint(c.x) << 32);
            const unsigned long long* sb =
                (const unsigned long long*)&sER[cur][0];

            float ew[NWT];
            float ss[4] = {0.f, 0.f, 0.f, 0.f};
            #pragma unroll
            for (int i = 0; i < NWT; i++) {
                // even-half window 2i ; odd-half window 2i+1 (dead slot -> w=0)
                const int we = 2 * i;
                const int wo = (2 * i + 1 < WIN) ? 2 * i + 1 : 0;
                const int offE = (we / 7) * H1W + (we % 7);
                const int offO = (wo / 7) * H1W + (wo % 7);
                const int off  = odd ? offO : offE;     // SEL, no branch
                unsigned long long nb = sb[wbase + off];
                unsigned long long p;
                asm("mul.rn.f32x2 %0, %1, %2;" : "=l"(p) : "l"(nb), "l"(cs));
                float e = fmaxf(__uint_as_float((unsigned)p),
                                __uint_as_float((unsigned)(p >> 32)));
                if (i == NWT - 1) e = odd ? 0.f : e;    // kill dead slot
                ew[i] = e;
                ss[i & 3] += e;
            }

            float ssl  = (ss[0] + ss[1]) + (ss[2] + ss[3]);
            float ssum = ssl + __shfl_xor_sync(0xFFFFFFFFu, ssl, 16);

            float scale = __fdividef(__ldg(cp + k), ssum);
            if (myM == 0.f) scale = 0.f;
            #pragma unroll
            for (int i = 0; i < NWT; i++) Aw[i] += scale * ew[i];
        }
        __syncthreads();
    }

    // store: thread's windows are w = 2*i + odd
    float* Ab = g_Apart + ((size_t)sl * BB + b) * WIN * NN * NN
              + gi * NN + gj;
    #pragma unroll
    for (int i = 0; i < NWT; i++) {
        const int w = 2 * i + (odd ? 1 : 0);
        if (w < WIN)
            Ab[(size_t)w * NN * NN] = Aw[i];
    }
}

// ================= reduce: g_A = sum over NS partials =================

#define RED_TOT4 (BB * WIN * NN * NN / 4)   // 401408 float4
#define RED_THR  256

__global__ __launch_bounds__(RED_THR)
void rwn_reduce_kernel()
{
    const int i = blockIdx.x * RED_THR + threadIdx.x;
    const float4* p = (const float4*)g_Apart;
    float4 r = p[i];
    #pragma unroll
    for (int s = 1; s < NS; s++) {
        float4 a = p[i + (size_t)s * RED_TOT4];
        r.x += a.x; r.y += a.y; r.z += a.z; r.w += a.w;
    }
    ((float4*)g_A)[i] = r;
}

// ================= kernel 2: gather (channel-grouped) =================
// y[q,c] = sum_w A[q-o_w, w] * x2[c, q-o_w]

#define T2H 16
#define T2W 16
#define NT2 (T2H * T2W)
#define H2  (T2H + 2 * RAD)       // 22
#define CG  7                     // channels per block
#define NG  (CCH / CG)            // 3 groups

__global__ __launch_bounds__(NT2)
void rwn_gather_kernel(const float* __restrict__ x2,   // [B,C,N*N]
                       float* __restrict__ out)        // [B,N*N,C]
{
    __shared__ float sX[CG][H2 * H2];   // 13552 B

    const int z  = blockIdx.z;
    const int b  = z % BB;
    const int cg = z / BB;
    const int bi = blockIdx.y * T2H;
    const int bj = blockIdx.x * T2W;
    const int t  = threadIdx.x;
    const int ti = t / T2W, tj = t % T2W;
    const int qi = bi + ti, qj = bj + tj;

    const float* xb = x2 + ((size_t)b * CCH + cg * CG) * NN * NN;
    for (int idx = t; idx < CG * H2 * H2; idx += NT2) {
        int c  = idx / (H2 * H2);
        int r  = idx % (H2 * H2);
        int hi = r / H2, hj = r % H2;
        int gi = bi + hi - RAD, gj = bj + hj - RAD;
        float v = 0.f;
        if (gi >= 0 && gi < NN && gj >= 0 && gj < NN)
            v = __ldg(xb + c * NN * NN + gi * NN + gj);
        sX[c][r] = v;
    }
    __syncthreads();

    float acc[CG];
    #pragma unroll
    for (int c = 0; c < CG; c++) acc[c] = 0.f;

    const float* Ab = g_A + (size_t)b * WIN * NN * NN;

    #pragma unroll
    for (int oi = -RAD; oi <= RAD; oi++) {
        #pragma unroll
        for (int oj = -RAD; oj <= RAD; oj++) {
            const int w  = (oi + RAD) * (2 * RAD + 1) + (oj + RAD);
            const int pi = qi - oi, pj = qj - oj;
            if (pi < 0 || pi >= NN || pj < 0 || pj >= NN) continue;
            const float a = __ldg(Ab + (size_t)w * NN * NN + pi * NN + pj);
            const int sidx = (ti + RAD - oi) * H2 + (tj + RAD - oj);
            #pragma unroll
            for (int c = 0; c < CG; c++)
                acc[c] += a * sX[c][sidx];
        }
    }

    float* ob = out + ((size_t)b * NN * NN + qi * NN + qj) * CCH + cg * CG;
    #pragma unroll
    for (int c = 0; c < CG; c++) ob[c] = acc[c];
}

// ================= launch =================
extern "C" void kernel_launch(void* const* d_in, const int* in_sizes, int n_in,
                              void* d_out, int out_size)
{
    const float* feats = (const float*)d_in[0];   // intergrated [B,K,N,N]
    const float* x2    = (const float*)d_in[1];   // [B,C,N*N]
    const int*   mask  = (const int*)  d_in[2];   // [B,N,N]
    const float* cp    = (const float*)d_in[3];   // [K]
    float*       out   = (float*)d_out;           // [B,N*N,C]

    dim3 g1(NN / T1W, NN / T1H, BB * NS);     // (8,16,14) = 1792 blocks
    rwn_weights_kernel<<<g1, NT1>>>(feats, mask, cp);

    rwn_reduce_kernel<<<RED_TOT4 / RED_THR, RED_THR>>>();   // 1568 blocks

    dim3 g2(NN / T2W, NN / T2H, BB * NG);     // (8,8,6) = 384 blocks
    rwn_gather_kernel<<<g2, NT2>>>(x2, out);
}